// round 2
// baseline (speedup 1.0000x reference)
#include <cuda_runtime.h>
#include <math.h>

#define S_LEN 2048
#define HID   2048
#define NH    16
#define NKV   4
#define HD    128
#define INTER 8192
#define ALPHA 0.7f
#define EPS_  1e-5f

// ---------------- scratch (static device allocations; allowed) ----------------
__device__ float g_wq[HID * HID];
__device__ float g_wk[NKV * HD * HID];
__device__ float g_wv[NKV * HD * HID];
__device__ float g_wo[HID * HID];
__device__ float g_wg[INTER * HID];
__device__ float g_wu[INTER * HID];
__device__ float g_wd[HID * INTER];
__device__ float g_h [S_LEN * HID];
__device__ float g_q [S_LEN * HID];
__device__ float g_k [S_LEN * NKV * HD];
__device__ float g_v [S_LEN * NKV * HD];
__device__ float g_o [S_LEN * HID];
__device__ float g_x2[S_LEN * HID];
__device__ float g_h2[S_LEN * HID];
__device__ float g_G [S_LEN * INTER];
__device__ float g_U [S_LEN * INTER];

// ---------------- ternary quantization: w' = ternary(w) * absmean -------------
// One block per output row; float4 vectorized (K is a multiple of 1024).
__global__ void quant_kernel(const float* __restrict__ w, float* __restrict__ o, int K) {
    int row = blockIdx.x;
    const float4* wr = (const float4*)(w + (size_t)row * K);
    float4* orow = (float4*)(o + (size_t)row * K);
    const int K4 = K >> 2;
    float s = 0.f;
    for (int i = threadIdx.x; i < K4; i += 256) {
        float4 v = wr[i];
        s += fabsf(v.x) + fabsf(v.y) + fabsf(v.z) + fabsf(v.w);
    }
    __shared__ float red[8];
    #pragma unroll
    for (int off = 16; off; off >>= 1) s += __shfl_down_sync(0xffffffffu, s, off);
    if ((threadIdx.x & 31) == 0) red[threadIdx.x >> 5] = s;
    __syncthreads();
    if (threadIdx.x == 0) {
        float t = 0.f;
        #pragma unroll
        for (int i = 0; i < 8; i++) t += red[i];
        red[0] = t;
    }
    __syncthreads();
    float absmean = red[0] / (float)K;
    float thr = ALPHA * absmean;
    for (int i = threadIdx.x; i < K4; i += 256) {
        float4 v = wr[i];
        float4 r;
        r.x = (fabsf(v.x) > thr) ? (v.x > 0.f ? absmean : -absmean) : 0.f;
        r.y = (fabsf(v.y) > thr) ? (v.y > 0.f ? absmean : -absmean) : 0.f;
        r.z = (fabsf(v.z) > thr) ? (v.z > 0.f ? absmean : -absmean) : 0.f;
        r.w = (fabsf(v.w) > thr) ? (v.w > 0.f ? absmean : -absmean) : 0.f;
        orow[i] = r;
    }
}

// ---------------- rmsnorm ------------------------------------------------------
__global__ void rmsnorm_kernel(const float* __restrict__ x, const float* __restrict__ w,
                               float* __restrict__ o) {
    int row = blockIdx.x;
    const float4* xr = (const float4*)(x + (size_t)row * HID);
    float4* orow = (float4*)(o + (size_t)row * HID);
    const float4* w4 = (const float4*)w;
    float s = 0.f;
    float4 v = xr[threadIdx.x];                 // HID/4 = 512 = 2*256
    float4 v2 = xr[threadIdx.x + 256];
    s = v.x * v.x + v.y * v.y + v.z * v.z + v.w * v.w
      + v2.x * v2.x + v2.y * v2.y + v2.z * v2.z + v2.w * v2.w;
    __shared__ float red[8];
    #pragma unroll
    for (int off = 16; off; off >>= 1) s += __shfl_down_sync(0xffffffffu, s, off);
    if ((threadIdx.x & 31) == 0) red[threadIdx.x >> 5] = s;
    __syncthreads();
    if (threadIdx.x == 0) {
        float t = 0.f;
        #pragma unroll
        for (int i = 0; i < 8; i++) t += red[i];
        red[0] = t;
    }
    __syncthreads();
    float inv = rsqrtf(red[0] / (float)HID + EPS_);
    float4 g1 = w4[threadIdx.x], g2 = w4[threadIdx.x + 256];
    float4 r1, r2;
    r1.x = v.x * inv * g1.x;  r1.y = v.y * inv * g1.y;
    r1.z = v.z * inv * g1.z;  r1.w = v.w * inv * g1.w;
    r2.x = v2.x * inv * g2.x; r2.y = v2.y * inv * g2.y;
    r2.z = v2.z * inv * g2.z; r2.w = v2.w * inv * g2.w;
    orow[threadIdx.x] = r1;
    orow[threadIdx.x + 256] = r2;
}

// ---------------- SGEMM: C[M,N] = A[M,K] * B[N,K]^T  (+ epilogues) -------------
// EPI 0: C = acc
// EPI 1: C = acc + Aux          (residual add)
// EPI 3: C = relu(acc)^2 * Aux  (squared-relu gate * up, fused)
template <int EPI>
__global__ void __launch_bounds__(256, 2)
sgemm_kernel(const float* __restrict__ A, const float* __restrict__ B,
             float* __restrict__ C, const float* __restrict__ Aux,
             int M, int N, int K) {
    __shared__ float As[8][128];
    __shared__ float Bs[8][128];
    const int bm = blockIdx.y * 128;
    const int bn = blockIdx.x * 128;
    const int t  = threadIdx.x;
    const int tx = t & 15;
    const int ty = t >> 4;
    const int lrow = t >> 1;
    const int lcol = (t & 1) * 4;

    float acc[8][8];
    #pragma unroll
    for (int i = 0; i < 8; i++)
        #pragma unroll
        for (int j = 0; j < 8; j++) acc[i][j] = 0.f;

    const float* Ap = A + (size_t)(bm + lrow) * K + lcol;
    const float* Bp = B + (size_t)(bn + lrow) * K + lcol;

    for (int k0 = 0; k0 < K; k0 += 8) {
        float4 a4 = *(const float4*)(Ap + k0);
        float4 b4 = *(const float4*)(Bp + k0);
        __syncthreads();
        As[lcol + 0][lrow] = a4.x; As[lcol + 1][lrow] = a4.y;
        As[lcol + 2][lrow] = a4.z; As[lcol + 3][lrow] = a4.w;
        Bs[lcol + 0][lrow] = b4.x; Bs[lcol + 1][lrow] = b4.y;
        Bs[lcol + 2][lrow] = b4.z; Bs[lcol + 3][lrow] = b4.w;
        __syncthreads();
        #pragma unroll
        for (int kk = 0; kk < 8; kk++) {
            float a[8], b[8];
            *(float4*)&a[0] = *(const float4*)&As[kk][ty * 8];
            *(float4*)&a[4] = *(const float4*)&As[kk][ty * 8 + 4];
            *(float4*)&b[0] = *(const float4*)&Bs[kk][tx * 8];
            *(float4*)&b[4] = *(const float4*)&Bs[kk][tx * 8 + 4];
            #pragma unroll
            for (int i = 0; i < 8; i++)
                #pragma unroll
                for (int j = 0; j < 8; j++)
                    acc[i][j] += a[i] * b[j];
        }
    }

    #pragma unroll
    for (int i = 0; i < 8; i++) {
        int row = bm + ty * 8 + i;
        #pragma unroll
        for (int j = 0; j < 8; j++) {
            int col = bn + tx * 8 + j;
            size_t idx = (size_t)row * N + col;
            float v = acc[i][j];
            if (EPI == 1) v += Aux[idx];
            if (EPI == 3) { v = fmaxf(v, 0.f); v = v * v * Aux[idx]; }
            C[idx] = v;
        }
    }
}

// ---------------- RoPE (in place) ---------------------------------------------
__global__ void rope_kernel(float* __restrict__ q, const float* __restrict__ cs,
                            const float* __restrict__ sn, int nheads) {
    int idx = blockIdx.x * 256 + threadIdx.x;
    int total = S_LEN * nheads * 64;
    if (idx >= total) return;
    int d  = idx & 63;
    int r  = idx >> 6;
    int hh = r % nheads;
    int s  = r / nheads;
    float c1 = cs[s * HD + d],      s1 = sn[s * HD + d];
    float c2 = cs[s * HD + d + 64], s2 = sn[s * HD + d + 64];
    float* row = q + (size_t)s * (nheads * HD) + hh * HD;
    float a = row[d], b = row[d + 64];
    row[d]      = a * c1 - b * s1;
    row[d + 64] = b * c2 + a * s2;
}

// ---------------- causal GQA flash attention ----------------------------------
// Block: 128 threads, handles 16 query rows of one head, tiles of 32 keys.
__global__ void __launch_bounds__(128)
attn_kernel(const float* __restrict__ Q, const float* __restrict__ Kg,
            const float* __restrict__ Vg, float* __restrict__ O) {
    const int q0  = blockIdx.x * 16;
    const int h   = blockIdx.y;
    const int kvh = h >> 2;
    const int tid = threadIdx.x;

    __shared__ float Qs[16][132];
    __shared__ float Ks[32][132];
    __shared__ float Vs[32][132];
    __shared__ float Ls[16][32];
    __shared__ float Ms[16], Lsum[16], Corr[16];

    #pragma unroll
    for (int r = 0; r < 16; r++)
        Qs[r][tid] = Q[(size_t)(q0 + r) * (NH * HD) + h * HD + tid];
    if (tid < 16) { Ms[tid] = -INFINITY; Lsum[tid] = 0.f; }

    float acc[16];
    #pragma unroll
    for (int i = 0; i < 16; i++) acc[i] = 0.f;

    const float scale = 0.088388347648318447f;  // 1/sqrt(128)
    const int kj = tid & 31;
    const int qb = tid >> 5;
    const int qmax = q0 + 15;

    for (int j0 = 0; j0 <= qmax; j0 += 32) {
        // load K/V tile (rows j0..j0+31, always < S_LEN)
        #pragma unroll 4
        for (int r = 0; r < 32; r++) {
            size_t base = (size_t)(j0 + r) * (NKV * HD) + kvh * HD + tid;
            Ks[r][tid] = Kg[base];
            Vs[r][tid] = Vg[base];
        }
        __syncthreads();

        // logits: thread -> key kj, 4 query rows qb*4..qb*4+3
        float d0 = 0.f, d1 = 0.f, d2 = 0.f, d3 = 0.f;
        #pragma unroll 8
        for (int d = 0; d < HD; d += 4) {
            float4 kv = *(const float4*)&Ks[kj][d];
            float4 a0 = *(const float4*)&Qs[qb * 4 + 0][d];
            float4 a1 = *(const float4*)&Qs[qb * 4 + 1][d];
            float4 a2 = *(const float4*)&Qs[qb * 4 + 2][d];
            float4 a3 = *(const float4*)&Qs[qb * 4 + 3][d];
            d0 += a0.x * kv.x + a0.y * kv.y + a0.z * kv.z + a0.w * kv.w;
            d1 += a1.x * kv.x + a1.y * kv.y + a1.z * kv.z + a1.w * kv.w;
            d2 += a2.x * kv.x + a2.y * kv.y + a2.z * kv.z + a2.w * kv.w;
            d3 += a3.x * kv.x + a3.y * kv.y + a3.z * kv.z + a3.w * kv.w;
        }
        const int kglob = j0 + kj;
        float dots[4] = {d0, d1, d2, d3};
        #pragma unroll
        for (int ii = 0; ii < 4; ii++) {
            int qi = qb * 4 + ii;
            float lg = dots[ii] * scale;
            if (kglob > q0 + qi) lg = -INFINITY;
            Ls[qi][kj] = lg;
        }
        __syncthreads();

        // per-row running max / correction (16 designated threads)
        if (tid < 16) {
            float tm = -INFINITY;
            #pragma unroll
            for (int jj = 0; jj < 32; jj++) tm = fmaxf(tm, Ls[tid][jj]);
            float mo = Ms[tid];
            float nm = fmaxf(mo, tm);
            Corr[tid] = expf(mo - nm);
            Ms[tid] = nm;
        }
        __syncthreads();

        // exponentiate logits in place
        #pragma unroll
        for (int e = tid; e < 512; e += 128) {
            int qi = e >> 5, jj = e & 31;
            Ls[qi][jj] = expf(Ls[qi][jj] - Ms[qi]);
        }
        __syncthreads();

        // row sums
        if (tid < 16) {
            float ts = 0.f;
            #pragma unroll
            for (int jj = 0; jj < 32; jj++) ts += Ls[tid][jj];
            Lsum[tid] = Lsum[tid] * Corr[tid] + ts;
        }

        // rescale + accumulate: thread owns dim tid for all 16 rows
        #pragma unroll
        for (int qi = 0; qi < 16; qi++) acc[qi] *= Corr[qi];
        #pragma unroll 4
        for (int jj = 0; jj < 32; jj++) {
            float vj = Vs[jj][tid];
            #pragma unroll
            for (int qi = 0; qi < 16; qi++) acc[qi] += Ls[qi][jj] * vj;
        }
        __syncthreads();
    }

    #pragma unroll
    for (int qi = 0; qi < 16; qi++)
        O[(size_t)(q0 + qi) * (NH * HD) + h * HD + tid] = acc[qi] / Lsum[qi];
}

// ---------------- launch -------------------------------------------------------
extern "C" void kernel_launch(void* const* d_in, const int* in_sizes, int n_in,
                              void* d_out, int out_size) {
    const float* x   = (const float*)d_in[0];
    const float* cs  = (const float*)d_in[1];
    const float* sn  = (const float*)d_in[2];
    const float* wq  = (const float*)d_in[3];
    const float* wk  = (const float*)d_in[4];
    const float* wv  = (const float*)d_in[5];
    const float* wo  = (const float*)d_in[6];
    const float* wg  = (const float*)d_in[7];
    const float* wu  = (const float*)d_in[8];
    const float* wd  = (const float*)d_in[9];
    const float* ln1 = (const float*)d_in[10];
    const float* ln2 = (const float*)d_in[11];
    float* out = (float*)d_out;

    float *p_wq, *p_wk, *p_wv, *p_wo, *p_wg, *p_wu, *p_wd;
    float *p_h, *p_q, *p_k, *p_v, *p_o, *p_x2, *p_h2, *p_G, *p_U;
    cudaGetSymbolAddress((void**)&p_wq, g_wq);
    cudaGetSymbolAddress((void**)&p_wk, g_wk);
    cudaGetSymbolAddress((void**)&p_wv, g_wv);
    cudaGetSymbolAddress((void**)&p_wo, g_wo);
    cudaGetSymbolAddress((void**)&p_wg, g_wg);
    cudaGetSymbolAddress((void**)&p_wu, g_wu);
    cudaGetSymbolAddress((void**)&p_wd, g_wd);
    cudaGetSymbolAddress((void**)&p_h,  g_h);
    cudaGetSymbolAddress((void**)&p_q,  g_q);
    cudaGetSymbolAddress((void**)&p_k,  g_k);
    cudaGetSymbolAddress((void**)&p_v,  g_v);
    cudaGetSymbolAddress((void**)&p_o,  g_o);
    cudaGetSymbolAddress((void**)&p_x2, g_x2);
    cudaGetSymbolAddress((void**)&p_h2, g_h2);
    cudaGetSymbolAddress((void**)&p_G,  g_G);
    cudaGetSymbolAddress((void**)&p_U,  g_U);

    // 1. quantize all weights (fold absmean in)
    quant_kernel<<<HID,      256>>>(wq, p_wq, HID);
    quant_kernel<<<NKV * HD, 256>>>(wk, p_wk, HID);
    quant_kernel<<<NKV * HD, 256>>>(wv, p_wv, HID);
    quant_kernel<<<HID,      256>>>(wo, p_wo, HID);
    quant_kernel<<<INTER,    256>>>(wg, p_wg, HID);
    quant_kernel<<<INTER,    256>>>(wu, p_wu, HID);
    quant_kernel<<<HID,      256>>>(wd, p_wd, INTER);

    // 2. attention half
    rmsnorm_kernel<<<S_LEN, 256>>>(x, ln1, p_h);
    dim3 gQ(HID / 128, S_LEN / 128);
    dim3 gKV((NKV * HD) / 128, S_LEN / 128);
    sgemm_kernel<0><<<gQ,  256>>>(p_h, p_wq, p_q, nullptr, S_LEN, HID, HID);
    sgemm_kernel<0><<<gKV, 256>>>(p_h, p_wk, p_k, nullptr, S_LEN, NKV * HD, HID);
    sgemm_kernel<0><<<gKV, 256>>>(p_h, p_wv, p_v, nullptr, S_LEN, NKV * HD, HID);
    rope_kernel<<<(S_LEN * NH  * 64) / 256, 256>>>(p_q, cs, sn, NH);
    rope_kernel<<<(S_LEN * NKV * 64) / 256, 256>>>(p_k, cs, sn, NKV);
    attn_kernel<<<dim3(S_LEN / 16, NH), 128>>>(p_q, p_k, p_v, p_o);
    sgemm_kernel<1><<<gQ, 256>>>(p_o, p_wo, p_x2, x, S_LEN, HID, HID);

    // 3. MLP half
    rmsnorm_kernel<<<S_LEN, 256>>>(p_x2, ln2, p_h2);
    dim3 gI(INTER / 128, S_LEN / 128);
    sgemm_kernel<0><<<gI, 256>>>(p_h2, p_wu, p_U, nullptr, S_LEN, INTER, HID);
    sgemm_kernel<3><<<gI, 256>>>(p_h2, p_wg, p_G, p_U, S_LEN, INTER, HID);  // relu(g)^2 * up
    sgemm_kernel<1><<<gQ, 256>>>(p_G, p_wd, out, p_x2, S_LEN, HID, INTER);
}

// round 5
// speedup vs baseline: 2.8006x; 2.8006x over previous
#include <cuda_runtime.h>
#include <cuda_bf16.h>
#include <math.h>
#include <stdint.h>

#define S_LEN 2048
#define HID   2048
#define NH    16
#define NKV   4
#define HD    128
#define INTER 8192
#define ALPHA 0.7f
#define EPS_  1e-5f

// ============================ PTX helpers (plain sm_100 target) ==============
__device__ __forceinline__ uint32_t smem_u32(const void* p) {
    uint32_t a;
    asm("{ .reg .u64 t; cvta.to.shared.u64 t, %1; cvt.u32.u64 %0, t; }" : "=r"(a) : "l"(p));
    return a;
}
#define CP_ASYNC16(dst, src) \
    asm volatile("cp.async.cg.shared.global [%0], [%1], 16;" :: "r"(dst), "l"(src))
#define CP_COMMIT()  asm volatile("cp.async.commit_group;" ::: "memory")
#define CP_WAIT(n)   asm volatile("cp.async.wait_group %0;" :: "n"(n) : "memory")

__device__ __forceinline__ void ldm_x4(uint32_t* r, uint32_t addr) {
    asm volatile("ldmatrix.sync.aligned.m8n8.x4.shared.b16 {%0,%1,%2,%3}, [%4];"
                 : "=r"(r[0]), "=r"(r[1]), "=r"(r[2]), "=r"(r[3]) : "r"(addr));
}
__device__ __forceinline__ void mma_bf16(float* c, const uint32_t* a, uint32_t b0, uint32_t b1) {
    asm volatile("mma.sync.aligned.m16n8k16.row.col.f32.bf16.bf16.f32 "
                 "{%0,%1,%2,%3}, {%4,%5,%6,%7}, {%8,%9}, {%0,%1,%2,%3};"
                 : "+f"(c[0]), "+f"(c[1]), "+f"(c[2]), "+f"(c[3])
                 : "r"(a[0]), "r"(a[1]), "r"(a[2]), "r"(a[3]), "r"(b0), "r"(b1));
}

// ============================ scratch ========================================
__device__ __nv_bfloat16 g_wqt[HID * HID];
__device__ __nv_bfloat16 g_wkt[NKV * HD * HID];
__device__ __nv_bfloat16 g_wvt[NKV * HD * HID];
__device__ __nv_bfloat16 g_wot[HID * HID];
__device__ __nv_bfloat16 g_wgt[INTER * HID];
__device__ __nv_bfloat16 g_wut[INTER * HID];
__device__ __nv_bfloat16 g_wdt[HID * INTER];
__device__ float g_swq[HID], g_swk[NKV * HD], g_swv[NKV * HD], g_swo[HID];
__device__ float g_swg[INTER], g_swu[INTER], g_swd[HID];
__device__ __nv_bfloat16 g_hhi[S_LEN * HID],  g_hlo[S_LEN * HID];
__device__ __nv_bfloat16 g_h2hi[S_LEN * HID], g_h2lo[S_LEN * HID];
__device__ __nv_bfloat16 g_ohi[S_LEN * HID],  g_olo[S_LEN * HID];
__device__ __nv_bfloat16 g_Ghi[S_LEN * INTER], g_Glo[S_LEN * INTER];
__device__ float g_q [S_LEN * HID];
__device__ float g_k [S_LEN * NKV * HD];
__device__ float g_v [S_LEN * NKV * HD];
__device__ float g_x2[S_LEN * HID];
__device__ float g_U [S_LEN * INTER];

// ============== ternary quantize -> exact bf16 {-1,0,1} + fp32 scale =========
__global__ void quant_kernel(const float* __restrict__ w, __nv_bfloat16* __restrict__ o,
                             float* __restrict__ sc, int K) {
    int row = blockIdx.x;
    const float4* wr = (const float4*)(w + (size_t)row * K);
    const int K4 = K >> 2;
    float s = 0.f;
    for (int i = threadIdx.x; i < K4; i += 256) {
        float4 v = wr[i];
        s += fabsf(v.x) + fabsf(v.y) + fabsf(v.z) + fabsf(v.w);
    }
    __shared__ float red[8];
    #pragma unroll
    for (int off = 16; off; off >>= 1) s += __shfl_down_sync(0xffffffffu, s, off);
    if ((threadIdx.x & 31) == 0) red[threadIdx.x >> 5] = s;
    __syncthreads();
    if (threadIdx.x == 0) {
        float t = 0.f;
        #pragma unroll
        for (int i = 0; i < 8; i++) t += red[i];
        red[0] = t;
    }
    __syncthreads();
    float absmean = red[0] / (float)K;
    float thr = ALPHA * absmean;
    if (threadIdx.x == 0) sc[row] = absmean;
    __nv_bfloat162* orow = (__nv_bfloat162*)(o + (size_t)row * K);
    for (int i = threadIdx.x; i < K4; i += 256) {
        float4 v = wr[i];
        float t0 = (fabsf(v.x) > thr) ? (v.x > 0.f ? 1.f : -1.f) : 0.f;
        float t1 = (fabsf(v.y) > thr) ? (v.y > 0.f ? 1.f : -1.f) : 0.f;
        float t2 = (fabsf(v.z) > thr) ? (v.z > 0.f ? 1.f : -1.f) : 0.f;
        float t3 = (fabsf(v.w) > thr) ? (v.w > 0.f ? 1.f : -1.f) : 0.f;
        orow[2 * i]     = __floats2bfloat162_rn(t0, t1);
        orow[2 * i + 1] = __floats2bfloat162_rn(t2, t3);
    }
}

// ============== rmsnorm -> split hi/lo bf16 ==================================
__global__ void rmsnorm_kernel(const float* __restrict__ x, const float* __restrict__ w,
                               __nv_bfloat16* __restrict__ ohi, __nv_bfloat16* __restrict__ olo) {
    int row = blockIdx.x;
    const float4* xr = (const float4*)(x + (size_t)row * HID);
    const float4* w4 = (const float4*)w;
    float4 v  = xr[threadIdx.x];
    float4 v2 = xr[threadIdx.x + 256];
    float s = v.x * v.x + v.y * v.y + v.z * v.z + v.w * v.w
            + v2.x * v2.x + v2.y * v2.y + v2.z * v2.z + v2.w * v2.w;
    __shared__ float red[8];
    #pragma unroll
    for (int off = 16; off; off >>= 1) s += __shfl_down_sync(0xffffffffu, s, off);
    if ((threadIdx.x & 31) == 0) red[threadIdx.x >> 5] = s;
    __syncthreads();
    if (threadIdx.x == 0) {
        float t = 0.f;
        #pragma unroll
        for (int i = 0; i < 8; i++) t += red[i];
        red[0] = t;
    }
    __syncthreads();
    float inv = rsqrtf(red[0] / (float)HID + EPS_);
    float4 g1 = w4[threadIdx.x], g2 = w4[threadIdx.x + 256];
    float y[8] = { v.x * inv * g1.x,  v.y * inv * g1.y,  v.z * inv * g1.z,  v.w * inv * g1.w,
                   v2.x * inv * g2.x, v2.y * inv * g2.y, v2.z * inv * g2.z, v2.w * inv * g2.w };
    size_t b0 = (size_t)row * HID + threadIdx.x * 4;
    size_t b1 = (size_t)row * HID + 1024 + threadIdx.x * 4;
    #pragma unroll
    for (int j = 0; j < 4; j++) {
        __nv_bfloat16 h = __float2bfloat16(y[j]);
        ohi[b0 + j] = h;
        olo[b0 + j] = __float2bfloat16(y[j] - __bfloat162float(h));
        __nv_bfloat16 h2 = __float2bfloat16(y[4 + j]);
        ohi[b1 + j] = h2;
        olo[b1 + j] = __float2bfloat16(y[4 + j] - __bfloat162float(h2));
    }
}

// ============== mma.sync GEMM: C[M,N] = (Ahi+Alo)[M,K] @ B[N,K]^T * scale[n] =
// Block 128x128, 8 warps (2x4), warp tile 64x32, ktile 32, 2-stage cp.async.
// Smem per stage: Ahi | Alo | B, each 128 rows x 32 bf16, pitch 40 bf16 (80B).
// EPI 0: C = acc*scale ; EPI 1: += Aux ; EPI 3: relu^2*Aux -> bf16 hi/lo
#define PITCH_B 80
#define ABUF    10240
#define STAGE   (3 * ABUF)

template <int EPI>
__global__ void __launch_bounds__(256, 1)
tc_gemm(const __nv_bfloat16* __restrict__ Ahi, const __nv_bfloat16* __restrict__ Alo,
        const __nv_bfloat16* __restrict__ Bw,  const float* __restrict__ scale,
        float* __restrict__ C, const float* __restrict__ Aux,
        __nv_bfloat16* __restrict__ Chi, __nv_bfloat16* __restrict__ Clo,
        int M, int N, int K) {
    extern __shared__ char smem[];
    const uint32_t sb = smem_u32(smem);
    const int tid = threadIdx.x;
    const int wid = tid >> 5;
    const int lid = tid & 31;
    const int wm  = wid >> 2;       // 0..1  (64 rows each)
    const int wn  = wid & 3;        // 0..3  (32 cols each)
    const int bm = blockIdx.y * 128;
    const int bn = blockIdx.x * 128;

    float acc[4][4][4];
    #pragma unroll
    for (int a = 0; a < 4; a++)
        #pragma unroll
        for (int b = 0; b < 4; b++)
            #pragma unroll
            for (int c = 0; c < 4; c++) acc[a][b][c] = 0.f;

    // -------- stage copy: 6 x 16B chunks per thread --------
    auto copy_stage = [&](int st, int k0) {
        uint32_t base = sb + st * STAGE;
        #pragma unroll
        for (int i = 0; i < 2; i++) {
            int c = tid + i * 256;           // 0..511
            int row = c >> 2, q = c & 3;
            size_t ga = (size_t)(bm + row) * K + k0 + q * 8;
            size_t gb = (size_t)(bn + row) * K + k0 + q * 8;
            uint32_t so = row * PITCH_B + q * 16;
            CP_ASYNC16(base + so,             Ahi + ga);
            CP_ASYNC16(base + ABUF + so,      Alo + ga);
            CP_ASYNC16(base + 2 * ABUF + so,  Bw  + gb);
        }
    };

    const int nk = K / 32;
    copy_stage(0, 0);
    CP_COMMIT();

    for (int s = 0; s < nk; s++) {
        if (s + 1 < nk) { copy_stage((s + 1) & 1, (s + 1) * 32); CP_COMMIT(); CP_WAIT(1); }
        else            { CP_WAIT(0); }
        __syncthreads();

        uint32_t aS = sb + (s & 1) * STAGE;
        uint32_t lS = aS + ABUF;
        uint32_t bS = aS + 2 * ABUF;
        #pragma unroll
        for (int kt = 0; kt < 2; kt++) {
            // B fragments: 2 x ldmatrix.x4 -> 4 n8k16 fragments
            uint32_t bfr[2][4];
            #pragma unroll
            for (int nt = 0; nt < 2; nt++) {
                int rowN = wn * 32 + nt * 16 + (lid & 7) + ((lid >> 4) << 3);
                ldm_x4(bfr[nt], bS + rowN * PITCH_B + kt * 32 + (((lid >> 3) & 1) << 4));
            }
            // hi pass
            {
                uint32_t afr[4][4];
                #pragma unroll
                for (int mt = 0; mt < 4; mt++) {
                    int rowM = wm * 64 + mt * 16 + (lid & 15);
                    ldm_x4(afr[mt], aS + rowM * PITCH_B + kt * 32 + ((lid >> 4) << 4));
                }
                #pragma unroll
                for (int mt = 0; mt < 4; mt++)
                    #pragma unroll
                    for (int g = 0; g < 4; g++)
                        mma_bf16(acc[mt][g], afr[mt], bfr[g >> 1][(g & 1) * 2], bfr[g >> 1][(g & 1) * 2 + 1]);
            }
            // lo pass (same B fragments)
            {
                uint32_t afr[4][4];
                #pragma unroll
                for (int mt = 0; mt < 4; mt++) {
                    int rowM = wm * 64 + mt * 16 + (lid & 15);
                    ldm_x4(afr[mt], lS + rowM * PITCH_B + kt * 32 + ((lid >> 4) << 4));
                }
                #pragma unroll
                for (int mt = 0; mt < 4; mt++)
                    #pragma unroll
                    for (int g = 0; g < 4; g++)
                        mma_bf16(acc[mt][g], afr[mt], bfr[g >> 1][(g & 1) * 2], bfr[g >> 1][(g & 1) * 2 + 1]);
            }
        }
        __syncthreads();
    }

    // -------- epilogue --------
    #pragma unroll
    for (int mt = 0; mt < 4; mt++) {
        int r0 = bm + wm * 64 + mt * 16 + (lid >> 2);
        #pragma unroll
        for (int g = 0; g < 4; g++) {
            int col = bn + wn * 32 + g * 8 + (lid & 3) * 2;
            float2 sc2 = *(const float2*)(scale + col);
            float v0 = acc[mt][g][0] * sc2.x;
            float v1 = acc[mt][g][1] * sc2.y;
            float v2 = acc[mt][g][2] * sc2.x;
            float v3 = acc[mt][g][3] * sc2.y;
            size_t i0 = (size_t)r0 * N + col;
            size_t i1 = (size_t)(r0 + 8) * N + col;
            if (EPI == 0) {
                *(float2*)(C + i0) = make_float2(v0, v1);
                *(float2*)(C + i1) = make_float2(v2, v3);
            } else if (EPI == 1) {
                float2 a0 = *(const float2*)(Aux + i0);
                float2 a1 = *(const float2*)(Aux + i1);
                *(float2*)(C + i0) = make_float2(v0 + a0.x, v1 + a0.y);
                *(float2*)(C + i1) = make_float2(v2 + a1.x, v3 + a1.y);
            } else {  // EPI 3
                float2 a0 = *(const float2*)(Aux + i0);
                float2 a1 = *(const float2*)(Aux + i1);
                float g0 = fmaxf(v0, 0.f); g0 = g0 * g0 * a0.x;
                float g1 = fmaxf(v1, 0.f); g1 = g1 * g1 * a0.y;
                float g2 = fmaxf(v2, 0.f); g2 = g2 * g2 * a1.x;
                float g3 = fmaxf(v3, 0.f); g3 = g3 * g3 * a1.y;
                __nv_bfloat16 h0 = __float2bfloat16(g0), h1 = __float2bfloat16(g1);
                __nv_bfloat16 h2 = __float2bfloat16(g2), h3 = __float2bfloat16(g3);
                *(__nv_bfloat162*)(Chi + i0) = __nv_bfloat162{h0, h1};
                *(__nv_bfloat162*)(Chi + i1) = __nv_bfloat162{h2, h3};
                *(__nv_bfloat162*)(Clo + i0) = __nv_bfloat162{
                    __float2bfloat16(g0 - __bfloat162float(h0)), __float2bfloat16(g1 - __bfloat162float(h1))};
                *(__nv_bfloat162*)(Clo + i1) = __nv_bfloat162{
                    __float2bfloat16(g2 - __bfloat162float(h2)), __float2bfloat16(g3 - __bfloat162float(h3))};
            }
        }
    }
}

// ============== RoPE (fp32, in place) ========================================
__global__ void rope_kernel(float* __restrict__ q, const float* __restrict__ cs,
                            const float* __restrict__ sn, int nheads) {
    int idx = blockIdx.x * 256 + threadIdx.x;
    int total = S_LEN * nheads * 64;
    if (idx >= total) return;
    int d  = idx & 63;
    int r  = idx >> 6;
    int hh = r % nheads;
    int s  = r / nheads;
    float c1 = cs[s * HD + d],      s1 = sn[s * HD + d];
    float c2 = cs[s * HD + d + 64], s2 = sn[s * HD + d + 64];
    float* row = q + (size_t)s * (nheads * HD) + hh * HD;
    float a = row[d], b = row[d + 64];
    row[d]      = a * c1 - b * s1;
    row[d + 64] = b * c2 + a * s2;
}

// ============== causal GQA flash attention (fp32) -> hi/lo bf16 out ==========
__global__ void __launch_bounds__(128)
attn_kernel(const float* __restrict__ Q, const float* __restrict__ Kg,
            const float* __restrict__ Vg, __nv_bfloat16* __restrict__ Ohi,
            __nv_bfloat16* __restrict__ Olo) {
    const int q0  = blockIdx.x * 16;
    const int h   = blockIdx.y;
    const int kvh = h >> 2;
    const int tid = threadIdx.x;

    __shared__ float Qs[16][132];
    __shared__ float Ks[32][132];
    __shared__ float Vs[32][132];
    __shared__ float Ls[16][32];
    __shared__ float Ms[16], Lsum[16], Corr[16];

    #pragma unroll
    for (int r = 0; r < 16; r++)
        Qs[r][tid] = Q[(size_t)(q0 + r) * (NH * HD) + h * HD + tid];
    if (tid < 16) { Ms[tid] = -INFINITY; Lsum[tid] = 0.f; }

    float acc[16];
    #pragma unroll
    for (int i = 0; i < 16; i++) acc[i] = 0.f;

    const float scale = 0.088388347648318447f;
    const int kj = tid & 31;
    const int qb = tid >> 5;
    const int qmax = q0 + 15;

    for (int j0 = 0; j0 <= qmax; j0 += 32) {
        #pragma unroll 4
        for (int r = 0; r < 32; r++) {
            size_t base = (size_t)(j0 + r) * (NKV * HD) + kvh * HD + tid;
            Ks[r][tid] = Kg[base];
            Vs[r][tid] = Vg[base];
        }
        __syncthreads();

        float d0 = 0.f, d1 = 0.f, d2 = 0.f, d3 = 0.f;
        #pragma unroll 8
        for (int d = 0; d < HD; d += 4) {
            float4 kv = *(const float4*)&Ks[kj][d];
            float4 a0 = *(const float4*)&Qs[qb * 4 + 0][d];
            float4 a1 = *(const float4*)&Qs[qb * 4 + 1][d];
            float4 a2 = *(const float4*)&Qs[qb * 4 + 2][d];
            float4 a3 = *(const float4*)&Qs[qb * 4 + 3][d];
            d0 += a0.x * kv.x + a0.y * kv.y + a0.z * kv.z + a0.w * kv.w;
            d1 += a1.x * kv.x + a1.y * kv.y + a1.z * kv.z + a1.w * kv.w;
            d2 += a2.x * kv.x + a2.y * kv.y + a2.z * kv.z + a2.w * kv.w;
            d3 += a3.x * kv.x + a3.y * kv.y + a3.z * kv.z + a3.w * kv.w;
        }
        const int kglob = j0 + kj;
        float dots[4] = {d0, d1, d2, d3};
        #pragma unroll
        for (int ii = 0; ii < 4; ii++) {
            int qi = qb * 4 + ii;
            float lg = dots[ii] * scale;
            if (kglob > q0 + qi) lg = -INFINITY;
            Ls[qi][kj] = lg;
        }
        __syncthreads();

        if (tid < 16) {
            float tm = -INFINITY;
            #pragma unroll
            for (int jj = 0; jj < 32; jj++) tm = fmaxf(tm, Ls[tid][jj]);
            float mo = Ms[tid];
            float nm = fmaxf(mo, tm);
            Corr[tid] = expf(mo - nm);
            Ms[tid] = nm;
        }
        __syncthreads();

        #pragma unroll
        for (int e = tid; e < 512; e += 128) {
            int qi = e >> 5, jj = e & 31;
            Ls[qi][jj] = expf(Ls[qi][jj] - Ms[qi]);
        }
        __syncthreads();

        if (tid < 16) {
            float ts = 0.f;
            #pragma unroll
            for (int jj = 0; jj < 32; jj++) ts += Ls[tid][jj];
            Lsum[tid] = Lsum[tid] * Corr[tid] + ts;
        }

        #pragma unroll
        for (int qi = 0; qi < 16; qi++) acc[qi] *= Corr[qi];
        #pragma unroll 4
        for (int jj = 0; jj < 32; jj++) {
            float vj = Vs[jj][tid];
            #pragma unroll
            for (int qi = 0; qi < 16; qi++) acc[qi] += Ls[qi][jj] * vj;
        }
        __syncthreads();
    }

    #pragma unroll
    for (int qi = 0; qi < 16; qi++) {
        float val = acc[qi] / Lsum[qi];
        size_t idx = (size_t)(q0 + qi) * (NH * HD) + h * HD + tid;
        __nv_bfloat16 hh = __float2bfloat16(val);
        Ohi[idx] = hh;
        Olo[idx] = __float2bfloat16(val - __bfloat162float(hh));
    }
}

// ============================ launch =========================================
extern "C" void kernel_launch(void* const* d_in, const int* in_sizes, int n_in,
                              void* d_out, int out_size) {
    const float* x   = (const float*)d_in[0];
    const float* cs  = (const float*)d_in[1];
    const float* sn  = (const float*)d_in[2];
    const float* wq  = (const float*)d_in[3];
    const float* wk  = (const float*)d_in[4];
    const float* wv  = (const float*)d_in[5];
    const float* wo  = (const float*)d_in[6];
    const float* wg  = (const float*)d_in[7];
    const float* wu  = (const float*)d_in[8];
    const float* wd  = (const float*)d_in[9];
    const float* ln1 = (const float*)d_in[10];
    const float* ln2 = (const float*)d_in[11];
    float* out = (float*)d_out;

    __nv_bfloat16 *p_wqt, *p_wkt, *p_wvt, *p_wot, *p_wgt, *p_wut, *p_wdt;
    float *p_swq, *p_swk, *p_swv, *p_swo, *p_swg, *p_swu, *p_swd;
    __nv_bfloat16 *p_hhi, *p_hlo, *p_h2hi, *p_h2lo, *p_ohi, *p_olo, *p_Ghi, *p_Glo;
    float *p_q, *p_k, *p_v, *p_x2, *p_U;
    cudaGetSymbolAddress((void**)&p_wqt, g_wqt);
    cudaGetSymbolAddress((void**)&p_wkt, g_wkt);
    cudaGetSymbolAddress((void**)&p_wvt, g_wvt);
    cudaGetSymbolAddress((void**)&p_wot, g_wot);
    cudaGetSymbolAddress((void**)&p_wgt, g_wgt);
    cudaGetSymbolAddress((void**)&p_wut, g_wut);
    cudaGetSymbolAddress((void**)&p_wdt, g_wdt);
    cudaGetSymbolAddress((void**)&p_swq, g_swq);
    cudaGetSymbolAddress((void**)&p_swk, g_swk);
    cudaGetSymbolAddress((void**)&p_swv, g_swv);
    cudaGetSymbolAddress((void**)&p_swo, g_swo);
    cudaGetSymbolAddress((void**)&p_swg, g_swg);
    cudaGetSymbolAddress((void**)&p_swu, g_swu);
    cudaGetSymbolAddress((void**)&p_swd, g_swd);
    cudaGetSymbolAddress((void**)&p_hhi, g_hhi);
    cudaGetSymbolAddress((void**)&p_hlo, g_hlo);
    cudaGetSymbolAddress((void**)&p_h2hi, g_h2hi);
    cudaGetSymbolAddress((void**)&p_h2lo, g_h2lo);
    cudaGetSymbolAddress((void**)&p_ohi, g_ohi);
    cudaGetSymbolAddress((void**)&p_olo, g_olo);
    cudaGetSymbolAddress((void**)&p_Ghi, g_Ghi);
    cudaGetSymbolAddress((void**)&p_Glo, g_Glo);
    cudaGetSymbolAddress((void**)&p_q,  g_q);
    cudaGetSymbolAddress((void**)&p_k,  g_k);
    cudaGetSymbolAddress((void**)&p_v,  g_v);
    cudaGetSymbolAddress((void**)&p_x2, g_x2);
    cudaGetSymbolAddress((void**)&p_U,  g_U);

    const int SMEM = 2 * STAGE;  // 61440
    cudaFuncSetAttribute(tc_gemm<0>, cudaFuncAttributeMaxDynamicSharedMemorySize, SMEM);
    cudaFuncSetAttribute(tc_gemm<1>, cudaFuncAttributeMaxDynamicSharedMemorySize, SMEM);
    cudaFuncSetAttribute(tc_gemm<3>, cudaFuncAttributeMaxDynamicSharedMemorySize, SMEM);

    // 1. quantize weights
    quant_kernel<<<HID,      256>>>(wq, p_wqt, p_swq, HID);
    quant_kernel<<<NKV * HD, 256>>>(wk, p_wkt, p_swk, HID);
    quant_kernel<<<NKV * HD, 256>>>(wv, p_wvt, p_swv, HID);
    quant_kernel<<<HID,      256>>>(wo, p_wot, p_swo, HID);
    quant_kernel<<<INTER,    256>>>(wg, p_wgt, p_swg, HID);
    quant_kernel<<<INTER,    256>>>(wu, p_wut, p_swu, HID);
    quant_kernel<<<HID,      256>>>(wd, p_wdt, p_swd, INTER);

    // 2. attention half
    rmsnorm_kernel<<<S_LEN, 256>>>(x, ln1, p_hhi, p_hlo);
    dim3 gQ(HID / 128, S_LEN / 128);            // (16,16)
    dim3 gKV((NKV * HD) / 128, S_LEN / 128);    // (4,16)
    tc_gemm<0><<<gQ,  256, SMEM>>>(p_hhi, p_hlo, p_wqt, p_swq, p_q, nullptr, nullptr, nullptr, S_LEN, HID, HID);
    tc_gemm<0><<<gKV, 256, SMEM>>>(p_hhi, p_hlo, p_wkt, p_swk, p_k, nullptr, nullptr, nullptr, S_LEN, NKV * HD, HID);
    tc_gemm<0><<<gKV, 256, SMEM>>>(p_hhi, p_hlo, p_wvt, p_swv, p_v, nullptr, nullptr, nullptr, S_LEN, NKV * HD, HID);
    rope_kernel<<<(S_LEN * NH  * 64) / 256, 256>>>(p_q, cs, sn, NH);
    rope_kernel<<<(S_LEN * NKV * 64) / 256, 256>>>(p_k, cs, sn, NKV);
    attn_kernel<<<dim3(S_LEN / 16, NH), 128>>>(p_q, p_k, p_v, p_ohi, p_olo);
    tc_gemm<1><<<gQ, 256, SMEM>>>(p_ohi, p_olo, p_wot, p_swo, p_x2, x, nullptr, nullptr, S_LEN, HID, HID);

    // 3. MLP half
    rmsnorm_kernel<<<S_LEN, 256>>>(p_x2, ln2, p_h2hi, p_h2lo);
    dim3 gI(INTER / 128, S_LEN / 128);          // (64,16)
    tc_gemm<0><<<gI, 256, SMEM>>>(p_h2hi, p_h2lo, p_wut, p_swu, p_U, nullptr, nullptr, nullptr, S_LEN, INTER, HID);
    tc_gemm<3><<<gI, 256, SMEM>>>(p_h2hi, p_h2lo, p_wgt, p_swg, nullptr, p_U, p_Ghi, p_Glo, S_LEN, INTER, HID);
    tc_gemm<1><<<gQ, 256, SMEM>>>(p_Ghi, p_Glo, p_wdt, p_swd, out, p_x2, nullptr, nullptr, S_LEN, HID, INTER);
}

// round 7
// speedup vs baseline: 3.5294x; 1.2603x over previous
#include <cuda_runtime.h>
#include <cuda_fp16.h>
#include <math.h>
#include <stdint.h>

#define S_LEN 2048
#define HID   2048
#define NH    16
#define NKV   4
#define HD    128
#define INTER 8192
#define NQKV  3072   // 2048 q + 512 k + 512 v
#define ALPHA 0.7f
#define EPS_  1e-5f

// ============================ PTX helpers (plain target) =====================
__device__ __forceinline__ uint32_t smem_u32(const void* p) {
    uint32_t a;
    asm("{ .reg .u64 t; cvta.to.shared.u64 t, %1; cvt.u32.u64 %0, t; }" : "=r"(a) : "l"(p));
    return a;
}
#define CP_ASYNC16(dst, src) \
    asm volatile("cp.async.cg.shared.global [%0], [%1], 16;" :: "r"(dst), "l"(src))
#define CP_COMMIT()  asm volatile("cp.async.commit_group;" ::: "memory")
#define CP_WAIT(n)   asm volatile("cp.async.wait_group %0;" :: "n"(n) : "memory")

__device__ __forceinline__ void ldm_x4(uint32_t* r, uint32_t addr) {
    asm volatile("ldmatrix.sync.aligned.m8n8.x4.shared.b16 {%0,%1,%2,%3}, [%4];"
                 : "=r"(r[0]), "=r"(r[1]), "=r"(r[2]), "=r"(r[3]) : "r"(addr));
}
__device__ __forceinline__ void mma_f16(float* c, const uint32_t* a, uint32_t b0, uint32_t b1) {
    asm volatile("mma.sync.aligned.m16n8k16.row.col.f32.f16.f16.f32 "
                 "{%0,%1,%2,%3}, {%4,%5,%6,%7}, {%8,%9}, {%0,%1,%2,%3};"
                 : "+f"(c[0]), "+f"(c[1]), "+f"(c[2]), "+f"(c[3])
                 : "r"(a[0]), "r"(a[1]), "r"(a[2]), "r"(a[3]), "r"(b0), "r"(b1));
}

// ============================ scratch ========================================
__device__ __half g_wqkv[NQKV * HID];
__device__ __half g_wot[HID * HID];
__device__ __half g_wgt[INTER * HID];
__device__ __half g_wut[INTER * HID];
__device__ __half g_wdt[HID * INTER];
__device__ float g_sqkv[NQKV], g_swo[HID], g_swg[INTER], g_swu[INTER], g_swd[HID];
__device__ __half g_hhi[S_LEN * HID], g_hlo[S_LEN * HID];
__device__ __half g_h2[S_LEN * HID];
__device__ __half g_o [S_LEN * HID];
__device__ __half g_G [S_LEN * INTER];
__device__ float g_qkv[S_LEN * NQKV];
__device__ float g_x2 [S_LEN * HID];
__device__ float g_U  [S_LEN * INTER];

// ============== ternary quantize -> exact fp16 {-1,0,1} + fp32 scale =========
__global__ void quant_kernel(const float* __restrict__ w, __half* __restrict__ o,
                             float* __restrict__ sc, int K) {
    int row = blockIdx.x;
    const float4* wr = (const float4*)(w + (size_t)row * K);
    const int K4 = K >> 2;
    float s = 0.f;
    for (int i = threadIdx.x; i < K4; i += 256) {
        float4 v = wr[i];
        s += fabsf(v.x) + fabsf(v.y) + fabsf(v.z) + fabsf(v.w);
    }
    __shared__ float red[8];
    #pragma unroll
    for (int off = 16; off; off >>= 1) s += __shfl_down_sync(0xffffffffu, s, off);
    if ((threadIdx.x & 31) == 0) red[threadIdx.x >> 5] = s;
    __syncthreads();
    if (threadIdx.x == 0) {
        float t = 0.f;
        #pragma unroll
        for (int i = 0; i < 8; i++) t += red[i];
        red[0] = t;
    }
    __syncthreads();
    float absmean = red[0] / (float)K;
    float thr = ALPHA * absmean;
    if (threadIdx.x == 0) sc[row] = absmean;
    __half2* orow = (__half2*)(o + (size_t)row * K);
    for (int i = threadIdx.x; i < K4; i += 256) {
        float4 v = wr[i];
        float t0 = (fabsf(v.x) > thr) ? (v.x > 0.f ? 1.f : -1.f) : 0.f;
        float t1 = (fabsf(v.y) > thr) ? (v.y > 0.f ? 1.f : -1.f) : 0.f;
        float t2 = (fabsf(v.z) > thr) ? (v.z > 0.f ? 1.f : -1.f) : 0.f;
        float t3 = (fabsf(v.w) > thr) ? (v.w > 0.f ? 1.f : -1.f) : 0.f;
        orow[2 * i]     = __floats2half2_rn(t0, t1);
        orow[2 * i + 1] = __floats2half2_rn(t2, t3);
    }
}

// ============== rmsnorm -> fp16 (optionally hi/lo split) =====================
template <bool SPLIT>
__global__ void rmsnorm_kernel(const float* __restrict__ x, const float* __restrict__ w,
                               __half* __restrict__ ohi, __half* __restrict__ olo) {
    int row = blockIdx.x;
    const float4* xr = (const float4*)(x + (size_t)row * HID);
    const float4* w4 = (const float4*)w;
    float4 v  = xr[threadIdx.x];
    float4 v2 = xr[threadIdx.x + 256];
    float s = v.x * v.x + v.y * v.y + v.z * v.z + v.w * v.w
            + v2.x * v2.x + v2.y * v2.y + v2.z * v2.z + v2.w * v2.w;
    __shared__ float red[8];
    #pragma unroll
    for (int off = 16; off; off >>= 1) s += __shfl_down_sync(0xffffffffu, s, off);
    if ((threadIdx.x & 31) == 0) red[threadIdx.x >> 5] = s;
    __syncthreads();
    if (threadIdx.x == 0) {
        float t = 0.f;
        #pragma unroll
        for (int i = 0; i < 8; i++) t += red[i];
        red[0] = t;
    }
    __syncthreads();
    float inv = rsqrtf(red[0] / (float)HID + EPS_);
    float4 g1 = w4[threadIdx.x], g2 = w4[threadIdx.x + 256];
    float y[8] = { v.x * inv * g1.x,  v.y * inv * g1.y,  v.z * inv * g1.z,  v.w * inv * g1.w,
                   v2.x * inv * g2.x, v2.y * inv * g2.y, v2.z * inv * g2.z, v2.w * inv * g2.w };
    size_t b0 = (size_t)row * HID + threadIdx.x * 4;
    size_t b1 = (size_t)row * HID + 1024 + threadIdx.x * 4;
    #pragma unroll
    for (int j = 0; j < 4; j++) {
        __half h = __float2half_rn(y[j]);
        ohi[b0 + j] = h;
        if (SPLIT) olo[b0 + j] = __float2half_rn(y[j] - __half2float(h));
        __half h2 = __float2half_rn(y[4 + j]);
        ohi[b1 + j] = h2;
        if (SPLIT) olo[b1 + j] = __float2half_rn(y[4 + j] - __half2float(h2));
    }
}

// ============== mma.sync GEMM ================================================
// C[M,N] = A[M,K] @ B[N,K]^T * scale[n], A = Ahi (+Alo if TWO).
// Block 128x128, 8 warps (2x4), warp tile 64x32, ktile 32, 3-stage cp.async.
// EPI 0: fp32 C = acc*scale ; EPI 1: fp32 C = acc*scale + Aux ;
// EPI 3: fp16 Ch = relu(acc*scale)^2 * Aux
#define PITCH_B 80
#define ABUF    10240

template <int EPI, bool TWO>
__global__ void __launch_bounds__(256, 1)
tc_gemm(const __half* __restrict__ Ahi, const __half* __restrict__ Alo,
        const __half* __restrict__ Bw,  const float* __restrict__ scale,
        float* __restrict__ C, const float* __restrict__ Aux,
        __half* __restrict__ Ch, int M, int N, int K) {
    constexpr int STAGE = (TWO ? 3 : 2) * ABUF;
    extern __shared__ char smem[];
    const uint32_t sb = smem_u32(smem);
    const int tid = threadIdx.x;
    const int lid = tid & 31;
    const int wid = tid >> 5;
    const int wm  = wid >> 2;
    const int wn  = wid & 3;
    const int bm = blockIdx.y * 128;
    const int bn = blockIdx.x * 128;

    float acc[4][4][4];
    #pragma unroll
    for (int a = 0; a < 4; a++)
        #pragma unroll
        for (int b = 0; b < 4; b++)
            #pragma unroll
            for (int c = 0; c < 4; c++) acc[a][b][c] = 0.f;

    auto copy_stage = [&](int st, int k0) {
        uint32_t base = sb + st * STAGE;
        #pragma unroll
        for (int i = 0; i < 2; i++) {
            int c = tid + i * 256;
            int row = c >> 2, q = c & 3;
            size_t ga = (size_t)(bm + row) * K + k0 + q * 8;
            size_t gb = (size_t)(bn + row) * K + k0 + q * 8;
            uint32_t so = row * PITCH_B + q * 16;
            CP_ASYNC16(base + so, Ahi + ga);
            if (TWO) CP_ASYNC16(base + ABUF + so, Alo + ga);
            CP_ASYNC16(base + (TWO ? 2 : 1) * ABUF + so, Bw + gb);
        }
    };

    const int nk = K / 32;
    copy_stage(0, 0);  CP_COMMIT();
    copy_stage(1, 32); CP_COMMIT();

    for (int s = 0; s < nk; s++) {
        if (s + 2 < nk) { copy_stage((s + 2) % 3, (s + 2) * 32); CP_COMMIT(); CP_WAIT(2); }
        else if (s + 1 < nk) { CP_WAIT(1); }
        else { CP_WAIT(0); }
        __syncthreads();

        uint32_t aS = sb + (s % 3) * STAGE;
        uint32_t bS = aS + (TWO ? 2 : 1) * ABUF;
        #pragma unroll
        for (int kt = 0; kt < 2; kt++) {
            uint32_t bfr[2][4];
            #pragma unroll
            for (int nt = 0; nt < 2; nt++) {
                int rowN = wn * 32 + nt * 16 + (lid & 7) + ((lid >> 4) << 3);
                ldm_x4(bfr[nt], bS + rowN * PITCH_B + kt * 32 + (((lid >> 3) & 1) << 4));
            }
            {
                uint32_t afr[4][4];
                #pragma unroll
                for (int mt = 0; mt < 4; mt++) {
                    int rowM = wm * 64 + mt * 16 + (lid & 15);
                    ldm_x4(afr[mt], aS + rowM * PITCH_B + kt * 32 + ((lid >> 4) << 4));
                }
                #pragma unroll
                for (int mt = 0; mt < 4; mt++)
                    #pragma unroll
                    for (int g = 0; g < 4; g++)
                        mma_f16(acc[mt][g], afr[mt], bfr[g >> 1][(g & 1) * 2], bfr[g >> 1][(g & 1) * 2 + 1]);
            }
            if (TWO) {
                uint32_t lS = aS + ABUF;
                uint32_t afr[4][4];
                #pragma unroll
                for (int mt = 0; mt < 4; mt++) {
                    int rowM = wm * 64 + mt * 16 + (lid & 15);
                    ldm_x4(afr[mt], lS + rowM * PITCH_B + kt * 32 + ((lid >> 4) << 4));
                }
                #pragma unroll
                for (int mt = 0; mt < 4; mt++)
                    #pragma unroll
                    for (int g = 0; g < 4; g++)
                        mma_f16(acc[mt][g], afr[mt], bfr[g >> 1][(g & 1) * 2], bfr[g >> 1][(g & 1) * 2 + 1]);
            }
        }
        __syncthreads();
    }

    #pragma unroll
    for (int mt = 0; mt < 4; mt++) {
        int r0 = bm + wm * 64 + mt * 16 + (lid >> 2);
        #pragma unroll
        for (int g = 0; g < 4; g++) {
            int col = bn + wn * 32 + g * 8 + (lid & 3) * 2;
            float2 sc2 = *(const float2*)(scale + col);
            float v0 = acc[mt][g][0] * sc2.x;
            float v1 = acc[mt][g][1] * sc2.y;
            float v2 = acc[mt][g][2] * sc2.x;
            float v3 = acc[mt][g][3] * sc2.y;
            size_t i0 = (size_t)r0 * N + col;
            size_t i1 = (size_t)(r0 + 8) * N + col;
            if (EPI == 0) {
                *(float2*)(C + i0) = make_float2(v0, v1);
                *(float2*)(C + i1) = make_float2(v2, v3);
            } else if (EPI == 1) {
                float2 a0 = *(const float2*)(Aux + i0);
                float2 a1 = *(const float2*)(Aux + i1);
                *(float2*)(C + i0) = make_float2(v0 + a0.x, v1 + a0.y);
                *(float2*)(C + i1) = make_float2(v2 + a1.x, v3 + a1.y);
            } else {
                float2 a0 = *(const float2*)(Aux + i0);
                float2 a1 = *(const float2*)(Aux + i1);
                float g0 = fmaxf(v0, 0.f); g0 = g0 * g0 * a0.x;
                float g1 = fmaxf(v1, 0.f); g1 = g1 * g1 * a0.y;
                float g2 = fmaxf(v2, 0.f); g2 = g2 * g2 * a1.x;
                float g3 = fmaxf(v3, 0.f); g3 = g3 * g3 * a1.y;
                *(__half2*)(Ch + i0) = __floats2half2_rn(g0, g1);
                *(__half2*)(Ch + i1) = __floats2half2_rn(g2, g3);
            }
        }
    }
}

// ============== RoPE (fp32, in place, strided) ===============================
__global__ void rope_kernel(float* __restrict__ q, const float* __restrict__ cs,
                            const float* __restrict__ sn, int nheads, int col_off) {
    int idx = blockIdx.x * 256 + threadIdx.x;
    int total = S_LEN * nheads * 64;
    if (idx >= total) return;
    int d  = idx & 63;
    int r  = idx >> 6;
    int hh = r % nheads;
    int s  = r / nheads;
    float c1 = cs[s * HD + d],      s1 = sn[s * HD + d];
    float c2 = cs[s * HD + d + 64], s2 = sn[s * HD + d + 64];
    float* row = q + (size_t)s * NQKV + col_off + hh * HD;
    float a = row[d], b = row[d + 64];
    row[d]      = a * c1 - b * s1;
    row[d + 64] = b * c2 + a * s2;
}

// ============== causal GQA flash attention (fp32 in, fp16 out) ===============
__global__ void __launch_bounds__(128)
attn_kernel(const float* __restrict__ QKV, __half* __restrict__ O) {
    const int q0  = blockIdx.x * 16;
    const int h   = blockIdx.y;
    const int kvh = h >> 2;
    const int tid = threadIdx.x;

    __shared__ float Qs[16][132];
    __shared__ float Ks[32][132];
    __shared__ float Vs[32][132];
    __shared__ float Ls[16][32];
    __shared__ float Ms[16], Lsum[16], Corr[16];

    #pragma unroll
    for (int r = 0; r < 16; r++)
        Qs[r][tid] = QKV[(size_t)(q0 + r) * NQKV + h * HD + tid];
    if (tid < 16) { Ms[tid] = -INFINITY; Lsum[tid] = 0.f; }

    float acc[16];
    #pragma unroll
    for (int i = 0; i < 16; i++) acc[i] = 0.f;

    const float scale = 0.088388347648318447f;
    const int kj = tid & 31;
    const int qb = tid >> 5;
    const int qmax = q0 + 15;

    for (int j0 = 0; j0 <= qmax; j0 += 32) {
        #pragma unroll 4
        for (int r = 0; r < 32; r++) {
            size_t base = (size_t)(j0 + r) * NQKV + kvh * HD + tid;
            Ks[r][tid] = QKV[base + 2048];
            Vs[r][tid] = QKV[base + 2560];
        }
        __syncthreads();

        float d0 = 0.f, d1 = 0.f, d2 = 0.f, d3 = 0.f;
        #pragma unroll 8
        for (int d = 0; d < HD; d += 4) {
            float4 kv = *(const float4*)&Ks[kj][d];
            float4 a0 = *(const float4*)&Qs[qb * 4 + 0][d];
            float4 a1 = *(const float4*)&Qs[qb * 4 + 1][d];
            float4 a2 = *(const float4*)&Qs[qb * 4 + 2][d];
            float4 a3 = *(const float4*)&Qs[qb * 4 + 3][d];
            d0 += a0.x * kv.x + a0.y * kv.y + a0.z * kv.z + a0.w * kv.w;
            d1 += a1.x * kv.x + a1.y * kv.y + a1.z * kv.z + a1.w * kv.w;
            d2 += a2.x * kv.x + a2.y * kv.y + a2.z * kv.z + a2.w * kv.w;
            d3 += a3.x * kv.x + a3.y * kv.y + a3.z * kv.z + a3.w * kv.w;
        }
        const int kglob = j0 + kj;
        float dots[4] = {d0, d1, d2, d3};
        #pragma unroll
        for (int ii = 0; ii < 4; ii++) {
            int qi = qb * 4 + ii;
            float lg = dots[ii] * scale;
            if (kglob > q0 + qi) lg = -INFINITY;
            Ls[qi][kj] = lg;
        }
        __syncthreads();

        if (tid < 16) {
            float tm = -INFINITY;
            #pragma unroll
            for (int jj = 0; jj < 32; jj++) tm = fmaxf(tm, Ls[tid][jj]);
            float mo = Ms[tid];
            float nm = fmaxf(mo, tm);
            Corr[tid] = expf(mo - nm);
            Ms[tid] = nm;
        }
        __syncthreads();

        #pragma unroll
        for (int e = tid; e < 512; e += 128) {
            int qi = e >> 5, jj = e & 31;
            Ls[qi][jj] = expf(Ls[qi][jj] - Ms[qi]);
        }
        __syncthreads();

        if (tid < 16) {
            float ts = 0.f;
            #pragma unroll
            for (int jj = 0; jj < 32; jj++) ts += Ls[tid][jj];
            Lsum[tid] = Lsum[tid] * Corr[tid] + ts;
        }

        #pragma unroll
        for (int qi = 0; qi < 16; qi++) acc[qi] *= Corr[qi];
        #pragma unroll 4
        for (int jj = 0; jj < 32; jj++) {
            float vj = Vs[jj][tid];
            #pragma unroll
            for (int qi = 0; qi < 16; qi++) acc[qi] += Ls[qi][jj] * vj;
        }
        __syncthreads();
    }

    #pragma unroll
    for (int qi = 0; qi < 16; qi++)
        O[(size_t)(q0 + qi) * (NH * HD) + h * HD + tid] = __float2half_rn(acc[qi] / Lsum[qi]);
}

// ============================ launch =========================================
extern "C" void kernel_launch(void* const* d_in, const int* in_sizes, int n_in,
                              void* d_out, int out_size) {
    const float* x   = (const float*)d_in[0];
    const float* cs  = (const float*)d_in[1];
    const float* sn  = (const float*)d_in[2];
    const float* wq  = (const float*)d_in[3];
    const float* wk  = (const float*)d_in[4];
    const float* wv  = (const float*)d_in[5];
    const float* wo  = (const float*)d_in[6];
    const float* wg  = (const float*)d_in[7];
    const float* wu  = (const float*)d_in[8];
    const float* wd  = (const float*)d_in[9];
    const float* ln1 = (const float*)d_in[10];
    const float* ln2 = (const float*)d_in[11];
    float* out = (float*)d_out;

    __half *p_wqkv, *p_wot, *p_wgt, *p_wut, *p_wdt;
    float *p_sqkv, *p_swo, *p_swg, *p_swu, *p_swd;
    __half *p_hhi, *p_hlo, *p_h2, *p_o, *p_G;
    float *p_qkv, *p_x2, *p_U;
    cudaGetSymbolAddress((void**)&p_wqkv, g_wqkv);
    cudaGetSymbolAddress((void**)&p_wot, g_wot);
    cudaGetSymbolAddress((void**)&p_wgt, g_wgt);
    cudaGetSymbolAddress((void**)&p_wut, g_wut);
    cudaGetSymbolAddress((void**)&p_wdt, g_wdt);
    cudaGetSymbolAddress((void**)&p_sqkv, g_sqkv);
    cudaGetSymbolAddress((void**)&p_swo, g_swo);
    cudaGetSymbolAddress((void**)&p_swg, g_swg);
    cudaGetSymbolAddress((void**)&p_swu, g_swu);
    cudaGetSymbolAddress((void**)&p_swd, g_swd);
    cudaGetSymbolAddress((void**)&p_hhi, g_hhi);
    cudaGetSymbolAddress((void**)&p_hlo, g_hlo);
    cudaGetSymbolAddress((void**)&p_h2,  g_h2);
    cudaGetSymbolAddress((void**)&p_o,   g_o);
    cudaGetSymbolAddress((void**)&p_G,   g_G);
    cudaGetSymbolAddress((void**)&p_qkv, g_qkv);
    cudaGetSymbolAddress((void**)&p_x2,  g_x2);
    cudaGetSymbolAddress((void**)&p_U,   g_U);

    cudaFuncSetAttribute(tc_gemm<0, true>,  cudaFuncAttributeMaxDynamicSharedMemorySize, 3 * 3 * ABUF);
    cudaFuncSetAttribute(tc_gemm<0, false>, cudaFuncAttributeMaxDynamicSharedMemorySize, 3 * 2 * ABUF);
    cudaFuncSetAttribute(tc_gemm<1, false>, cudaFuncAttributeMaxDynamicSharedMemorySize, 3 * 2 * ABUF);
    cudaFuncSetAttribute(tc_gemm<3, false>, cudaFuncAttributeMaxDynamicSharedMemorySize, 3 * 2 * ABUF);
    const int SM2 = 3 * 3 * ABUF;   // two-pass stages (92160)
    const int SM1 = 3 * 2 * ABUF;   // single-pass stages (61440)

    // ---- launch order chosen so launch #6 (ncu -s 5 -c 1) is the QKV GEMM ----
    quant_kernel<<<HID,      256>>>(wq, p_wqkv,                       p_sqkv,        HID);  // 1
    quant_kernel<<<NKV * HD, 256>>>(wk, p_wqkv + (size_t)2048 * HID,  p_sqkv + 2048, HID);  // 2
    quant_kernel<<<NKV * HD, 256>>>(wv, p_wqkv + (size_t)2560 * HID,  p_sqkv + 2560, HID);  // 3
    rmsnorm_kernel<true><<<S_LEN, 256>>>(x, ln1, p_hhi, p_hlo);                             // 4
    quant_kernel<<<HID,      256>>>(wo, p_wot, p_swo, HID);                                 // 5
    dim3 gQKV(NQKV / 128, S_LEN / 128);   // (24,16)
    tc_gemm<0, true><<<gQKV, 256, SM2>>>(p_hhi, p_hlo, p_wqkv, p_sqkv,                      // 6 (profiled)
                                         p_qkv, nullptr, nullptr, S_LEN, NQKV, HID);
    quant_kernel<<<INTER, 256>>>(wg, p_wgt, p_swg, HID);                                    // 7
    quant_kernel<<<INTER, 256>>>(wu, p_wut, p_swu, HID);                                    // 8
    quant_kernel<<<HID,   256>>>(wd, p_wdt, p_swd, INTER);                                  // 9
    rope_kernel<<<(S_LEN * NH  * 64) / 256, 256>>>(p_qkv, cs, sn, NH, 0);                   // 10
    rope_kernel<<<(S_LEN * NKV * 64) / 256, 256>>>(p_qkv, cs, sn, NKV, 2048);               // 11
    attn_kernel<<<dim3(S_LEN / 16, NH), 128>>>(p_qkv, p_o);                                 // 12
    dim3 gO(HID / 128, S_LEN / 128);
    tc_gemm<1, false><<<gO, 256, SM1>>>(p_o, nullptr, p_wot, p_swo,                         // 13
                                        p_x2, x, nullptr, S_LEN, HID, HID);
    rmsnorm_kernel<false><<<S_LEN, 256>>>(p_x2, ln2, p_h2, nullptr);                        // 14
    dim3 gI(INTER / 128, S_LEN / 128);
    tc_gemm<0, false><<<gI, 256, SM1>>>(p_h2, nullptr, p_wut, p_swu,                        // 15
                                        p_U, nullptr, nullptr, S_LEN, INTER, HID);
    tc_gemm<3, false><<<gI, 256, SM1>>>(p_h2, nullptr, p_wgt, p_swg,                        // 16
                                        nullptr, p_U, p_G, S_LEN, INTER, HID);
    tc_gemm<1, false><<<gO, 256, SM1>>>(p_G, nullptr, p_wdt, p_swd,                         // 17
                                        out, p_x2, nullptr, S_LEN, HID, INTER);
}

// round 10
// speedup vs baseline: 3.6871x; 1.0447x over previous
#include <cuda_runtime.h>
#include <cuda_fp16.h>
#include <math.h>
#include <stdint.h>

#define S_LEN 2048
#define HID   2048
#define NH    16
#define NKV   4
#define HD    128
#define INTER 8192
#define NQKV  3072   // 2048 q + 512 k + 512 v
#define ALPHA 0.7f
#define EPS_  1e-5f

// ============================ PTX helpers (plain target) =====================
__device__ __forceinline__ uint32_t smem_u32(const void* p) {
    uint32_t a;
    asm("{ .reg .u64 t; cvta.to.shared.u64 t, %1; cvt.u32.u64 %0, t; }" : "=r"(a) : "l"(p));
    return a;
}
#define CP_ASYNC16(dst, src) \
    asm volatile("cp.async.cg.shared.global [%0], [%1], 16;" :: "r"(dst), "l"(src))
#define CP_COMMIT()  asm volatile("cp.async.commit_group;" ::: "memory")
#define CP_WAIT(n)   asm volatile("cp.async.wait_group %0;" :: "n"(n) : "memory")

__device__ __forceinline__ void ldm_x4(uint32_t* r, uint32_t addr) {
    asm volatile("ldmatrix.sync.aligned.m8n8.x4.shared.b16 {%0,%1,%2,%3}, [%4];"
                 : "=r"(r[0]), "=r"(r[1]), "=r"(r[2]), "=r"(r[3]) : "r"(addr));
}
__device__ __forceinline__ void mma_f16(float* c, const uint32_t* a, uint32_t b0, uint32_t b1) {
    asm volatile("mma.sync.aligned.m16n8k16.row.col.f32.f16.f16.f32 "
                 "{%0,%1,%2,%3}, {%4,%5,%6,%7}, {%8,%9}, {%0,%1,%2,%3};"
                 : "+f"(c[0]), "+f"(c[1]), "+f"(c[2]), "+f"(c[3])
                 : "r"(a[0]), "r"(a[1]), "r"(a[2]), "r"(a[3]), "r"(b0), "r"(b1));
}

// ============================ scratch ========================================
__device__ __half g_wqkv[NQKV * HID];
__device__ __half g_wot[HID * HID];
__device__ __half g_wgt[INTER * HID];
__device__ __half g_wut[INTER * HID];
__device__ __half g_wdt[HID * INTER];
__device__ float g_sqkv[NQKV], g_swo[HID], g_swg[INTER], g_swu[INTER], g_swd[HID];
__device__ __half g_hhi[S_LEN * HID], g_hlo[S_LEN * HID];
__device__ __half g_h2[S_LEN * HID];
__device__ __half g_o [S_LEN * HID];
__device__ __half g_G [S_LEN * INTER];
__device__ float g_qkv[S_LEN * NQKV];
__device__ float g_x2 [S_LEN * HID];
__device__ float g_U  [S_LEN * INTER];

// ============== ternary quantize -> exact fp16 {-1,0,1} + fp32 scale =========
__device__ __forceinline__ void quant_row(const float* __restrict__ src,
                                          __half* __restrict__ dst,
                                          float* __restrict__ sc, int row, int K) {
    const float4* wr = (const float4*)src;
    const int K4 = K >> 2;
    float s = 0.f;
    for (int i = threadIdx.x; i < K4; i += 256) {
        float4 v = wr[i];
        s += fabsf(v.x) + fabsf(v.y) + fabsf(v.z) + fabsf(v.w);
    }
    __shared__ float red[8];
    #pragma unroll
    for (int off = 16; off; off >>= 1) s += __shfl_down_sync(0xffffffffu, s, off);
    if ((threadIdx.x & 31) == 0) red[threadIdx.x >> 5] = s;
    __syncthreads();
    if (threadIdx.x == 0) {
        float t = 0.f;
        #pragma unroll
        for (int i = 0; i < 8; i++) t += red[i];
        red[0] = t;
    }
    __syncthreads();
    float absmean = red[0] / (float)K;
    float thr = ALPHA * absmean;
    if (threadIdx.x == 0) sc[row] = absmean;
    __half2* orow = (__half2*)dst;
    for (int i = threadIdx.x; i < K4; i += 256) {
        float4 v = wr[i];
        float t0 = (fabsf(v.x) > thr) ? (v.x > 0.f ? 1.f : -1.f) : 0.f;
        float t1 = (fabsf(v.y) > thr) ? (v.y > 0.f ? 1.f : -1.f) : 0.f;
        float t2 = (fabsf(v.z) > thr) ? (v.z > 0.f ? 1.f : -1.f) : 0.f;
        float t3 = (fabsf(v.w) > thr) ? (v.w > 0.f ? 1.f : -1.f) : 0.f;
        orow[2 * i]     = __floats2half2_rn(t0, t1);
        orow[2 * i + 1] = __floats2half2_rn(t2, t3);
    }
}

__global__ void quant_kernel(const float* __restrict__ w, __half* __restrict__ o,
                             float* __restrict__ sc, int K) {
    int row = blockIdx.x;
    quant_row(w + (size_t)row * K, o + (size_t)row * K, sc, row, K);
}

// fused q|k|v quant: rows [0,2048) = wq, [2048,2560) = wk, [2560,3072) = wv
__global__ void quant_qkv_kernel(const float* __restrict__ wq, const float* __restrict__ wk,
                                 const float* __restrict__ wv, __half* __restrict__ o,
                                 float* __restrict__ sc) {
    int row = blockIdx.x;
    const float* src = (row < 2048) ? wq + (size_t)row * HID
                     : (row < 2560) ? wk + (size_t)(row - 2048) * HID
                                    : wv + (size_t)(row - 2560) * HID;
    quant_row(src, o + (size_t)row * HID, sc, row, HID);
}

// ============== rmsnorm -> fp16 (optionally hi/lo split) =====================
template <bool SPLIT>
__global__ void rmsnorm_kernel(const float* __restrict__ x, const float* __restrict__ w,
                               __half* __restrict__ ohi, __half* __restrict__ olo) {
    int row = blockIdx.x;
    const float4* xr = (const float4*)(x + (size_t)row * HID);
    const float4* w4 = (const float4*)w;
    float4 v  = xr[threadIdx.x];
    float4 v2 = xr[threadIdx.x + 256];
    float s = v.x * v.x + v.y * v.y + v.z * v.z + v.w * v.w
            + v2.x * v2.x + v2.y * v2.y + v2.z * v2.z + v2.w * v2.w;
    __shared__ float red[8];
    #pragma unroll
    for (int off = 16; off; off >>= 1) s += __shfl_down_sync(0xffffffffu, s, off);
    if ((threadIdx.x & 31) == 0) red[threadIdx.x >> 5] = s;
    __syncthreads();
    if (threadIdx.x == 0) {
        float t = 0.f;
        #pragma unroll
        for (int i = 0; i < 8; i++) t += red[i];
        red[0] = t;
    }
    __syncthreads();
    float inv = rsqrtf(red[0] / (float)HID + EPS_);
    float4 g1 = w4[threadIdx.x], g2 = w4[threadIdx.x + 256];
    float y[8] = { v.x * inv * g1.x,  v.y * inv * g1.y,  v.z * inv * g1.z,  v.w * inv * g1.w,
                   v2.x * inv * g2.x, v2.y * inv * g2.y, v2.z * inv * g2.z, v2.w * inv * g2.w };
    size_t b0 = (size_t)row * HID + threadIdx.x * 4;
    size_t b1 = (size_t)row * HID + 1024 + threadIdx.x * 4;
    #pragma unroll
    for (int j = 0; j < 4; j++) {
        __half h = __float2half_rn(y[j]);
        ohi[b0 + j] = h;
        if (SPLIT) olo[b0 + j] = __float2half_rn(y[j] - __half2float(h));
        __half h2 = __float2half_rn(y[4 + j]);
        ohi[b1 + j] = h2;
        if (SPLIT) olo[b1 + j] = __float2half_rn(y[4 + j] - __half2float(h2));
    }
}

// ============== mma.sync GEMM ================================================
// C[M,N] = A[M,K] @ B[N,K]^T * scale[n], A = Ahi (+Alo if TWO).
// Block 128x256, 8 warps (2x4), warp tile 64x64, ktile 32, 3-stage cp.async.
// EPI 0: fp32 C = acc*scale ; EPI 1: fp32 += Aux ;
// EPI 3: fp16 Ch = relu(acc*scale)^2 * Aux
#define PITCH_B 80
#define ABUF    10240   // 128 rows * 80 B
#define BBUF    20480   // 256 rows * 80 B

template <int EPI, bool TWO>
__global__ void __launch_bounds__(256, 1)
tc_gemm(const __half* __restrict__ Ahi, const __half* __restrict__ Alo,
        const __half* __restrict__ Bw,  const float* __restrict__ scale,
        float* __restrict__ C, const float* __restrict__ Aux,
        __half* __restrict__ Ch, int M, int N, int K) {
    constexpr int STAGE = (TWO ? 2 : 1) * ABUF + BBUF;
    extern __shared__ char smem[];
    const uint32_t sb = smem_u32(smem);
    const int tid = threadIdx.x;
    const int lid = tid & 31;
    const int wid = tid >> 5;     // 0..7
    const int wm  = wid >> 2;     // 0..1 (64 rows each)
    const int wn  = wid & 3;      // 0..3 (64 cols each)
    const int bm = blockIdx.y * 128;
    const int bn = blockIdx.x * 256;

    float acc[4][8][4];
    #pragma unroll
    for (int a = 0; a < 4; a++)
        #pragma unroll
        for (int b = 0; b < 8; b++)
            #pragma unroll
            for (int c = 0; c < 4; c++) acc[a][b][c] = 0.f;

    auto copy_stage = [&](int st, int k0) {
        uint32_t base = sb + st * STAGE;
        // A (and Alo): 128 rows x 4 chunks = 512
        #pragma unroll
        for (int i = 0; i < 2; i++) {
            int c = tid + i * 256;
            int row = c >> 2, q = c & 3;
            size_t ga = (size_t)(bm + row) * K + k0 + q * 8;
            uint32_t so = row * PITCH_B + q * 16;
            CP_ASYNC16(base + so, Ahi + ga);
            if (TWO) CP_ASYNC16(base + ABUF + so, Alo + ga);
        }
        // B: 256 rows x 4 chunks = 1024
        uint32_t bbase = base + (TWO ? 2 : 1) * ABUF;
        #pragma unroll
        for (int i = 0; i < 4; i++) {
            int c = tid + i * 256;
            int row = c >> 2, q = c & 3;
            size_t gb = (size_t)(bn + row) * K + k0 + q * 8;
            uint32_t so = row * PITCH_B + q * 16;
            CP_ASYNC16(bbase + so, Bw + gb);
        }
    };

    const int nk = K / 32;
    copy_stage(0, 0);  CP_COMMIT();
    copy_stage(1, 32); CP_COMMIT();

    for (int s = 0; s < nk; s++) {
        if (s + 2 < nk) { copy_stage((s + 2) % 3, (s + 2) * 32); CP_COMMIT(); CP_WAIT(2); }
        else if (s + 1 < nk) { CP_WAIT(1); }
        else { CP_WAIT(0); }
        __syncthreads();

        uint32_t aS = sb + (s % 3) * STAGE;
        uint32_t bS = aS + (TWO ? 2 : 1) * ABUF;
        #pragma unroll
        for (int kt = 0; kt < 2; kt++) {
            uint32_t bfr[4][4];
            #pragma unroll
            for (int nt = 0; nt < 4; nt++) {
                int rowN = wn * 64 + nt * 16 + (lid & 7) + ((lid >> 4) << 3);
                ldm_x4(bfr[nt], bS + rowN * PITCH_B + kt * 32 + (((lid >> 3) & 1) << 4));
            }
            {
                uint32_t afr[4][4];
                #pragma unroll
                for (int mt = 0; mt < 4; mt++) {
                    int rowM = wm * 64 + mt * 16 + (lid & 15);
                    ldm_x4(afr[mt], aS + rowM * PITCH_B + kt * 32 + ((lid >> 4) << 4));
                }
                #pragma unroll
                for (int mt = 0; mt < 4; mt++)
                    #pragma unroll
                    for (int g = 0; g < 8; g++)
                        mma_f16(acc[mt][g], afr[mt], bfr[g >> 1][(g & 1) * 2], bfr[g >> 1][(g & 1) * 2 + 1]);
            }
            if (TWO) {
                uint32_t lS = aS + ABUF;
                uint32_t afr[4][4];
                #pragma unroll
                for (int mt = 0; mt < 4; mt++) {
                    int rowM = wm * 64 + mt * 16 + (lid & 15);
                    ldm_x4(afr[mt], lS + rowM * PITCH_B + kt * 32 + ((lid >> 4) << 4));
                }
                #pragma unroll
                for (int mt = 0; mt < 4; mt++)
                    #pragma unroll
                    for (int g = 0; g < 8; g++)
                        mma_f16(acc[mt][g], afr[mt], bfr[g >> 1][(g & 1) * 2], bfr[g >> 1][(g & 1) * 2 + 1]);
            }
        }
        __syncthreads();
    }

    #pragma unroll
    for (int mt = 0; mt < 4; mt++) {
        int r0 = bm + wm * 64 + mt * 16 + (lid >> 2);
        #pragma unroll
        for (int g = 0; g < 8; g++) {
            int col = bn + wn * 64 + g * 8 + (lid & 3) * 2;
            float2 sc2 = *(const float2*)(scale + col);
            float v0 = acc[mt][g][0] * sc2.x;
            float v1 = acc[mt][g][1] * sc2.y;
            float v2 = acc[mt][g][2] * sc2.x;
            float v3 = acc[mt][g][3] * sc2.y;
            size_t i0 = (size_t)r0 * N + col;
            size_t i1 = (size_t)(r0 + 8) * N + col;
            if (EPI == 0) {
                *(float2*)(C + i0) = make_float2(v0, v1);
                *(float2*)(C + i1) = make_float2(v2, v3);
            } else if (EPI == 1) {
                float2 a0 = *(const float2*)(Aux + i0);
                float2 a1 = *(const float2*)(Aux + i1);
                *(float2*)(C + i0) = make_float2(v0 + a0.x, v1 + a0.y);
                *(float2*)(C + i1) = make_float2(v2 + a1.x, v3 + a1.y);
            } else {
                float2 a0 = *(const float2*)(Aux + i0);
                float2 a1 = *(const float2*)(Aux + i1);
                float g0 = fmaxf(v0, 0.f); g0 = g0 * g0 * a0.x;
                float g1 = fmaxf(v1, 0.f); g1 = g1 * g1 * a0.y;
                float g2 = fmaxf(v2, 0.f); g2 = g2 * g2 * a1.x;
                float g3 = fmaxf(v3, 0.f); g3 = g3 * g3 * a1.y;
                *(__half2*)(Ch + i0) = __floats2half2_rn(g0, g1);
                *(__half2*)(Ch + i1) = __floats2half2_rn(g2, g3);
            }
        }
    }
}

// ============== RoPE (fp32, in place, strided) ===============================
__global__ void rope_kernel(float* __restrict__ q, const float* __restrict__ cs,
                            const float* __restrict__ sn, int nheads, int col_off) {
    int idx = blockIdx.x * 256 + threadIdx.x;
    int total = S_LEN * nheads * 64;
    if (idx >= total) return;
    int d  = idx & 63;
    int r  = idx >> 6;
    int hh = r % nheads;
    int s  = r / nheads;
    float c1 = cs[s * HD + d],      s1 = sn[s * HD + d];
    float c2 = cs[s * HD + d + 64], s2 = sn[s * HD + d + 64];
    float* row = q + (size_t)s * NQKV + col_off + hh * HD;
    float a = row[d], b = row[d + 64];
    row[d]      = a * c1 - b * s1;
    row[d + 64] = b * c2 + a * s2;
}

// ============== causal GQA flash attention (fp32 in, fp16 out) ===============
__global__ void __launch_bounds__(128)
attn_kernel(const float* __restrict__ QKV, __half* __restrict__ O) {
    const int q0  = blockIdx.x * 16;
    const int h   = blockIdx.y;
    const int kvh = h >> 2;
    const int tid = threadIdx.x;

    __shared__ float Qs[16][132];
    __shared__ float Ks[32][132];
    __shared__ float Vs[32][132];
    __shared__ float Ls[16][32];
    __shared__ float Ms[16], Lsum[16], Corr[16];

    #pragma unroll
    for (int r = 0; r < 16; r++)
        Qs[r][tid] = QKV[(size_t)(q0 + r) * NQKV + h * HD + tid];
    if (tid < 16) { Ms[tid] = -INFINITY; Lsum[tid] = 0.f; }

    float acc[16];
    #pragma unroll
    for (int i = 0; i < 16; i++) acc[i] = 0.f;

    const float scale = 0.088388347648318447f;
    const int kj = tid & 31;
    const int qb = tid >> 5;
    const int qmax = q0 + 15;

    for (int j0 = 0; j0 <= qmax; j0 += 32) {
        #pragma unroll 4
        for (int r = 0; r < 32; r++) {
            size_t base = (size_t)(j0 + r) * NQKV + kvh * HD + tid;
            Ks[r][tid] = QKV[base + 2048];
            Vs[r][tid] = QKV[base + 2560];
        }
        __syncthreads();

        float d0 = 0.f, d1 = 0.f, d2 = 0.f, d3 = 0.f;
        #pragma unroll 8
        for (int d = 0; d < HD; d += 4) {
            float4 kv = *(const float4*)&Ks[kj][d];
            float4 a0 = *(const float4*)&Qs[qb * 4 + 0][d];
            float4 a1 = *(const float4*)&Qs[qb * 4 + 1][d];
            float4 a2 = *(const float4*)&Qs[qb * 4 + 2][d];
            float4 a3 = *(const float4*)&Qs[qb * 4 + 3][d];
            d0 += a0.x * kv.x + a0.y * kv.y + a0.z * kv.z + a0.w * kv.w;
            d1 += a1.x * kv.x + a1.y * kv.y + a1.z * kv.z + a1.w * kv.w;
            d2 += a2.x * kv.x + a2.y * kv.y + a2.z * kv.z + a2.w * kv.w;
            d3 += a3.x * kv.x + a3.y * kv.y + a3.z * kv.z + a3.w * kv.w;
        }
        const int kglob = j0 + kj;
        float dots[4] = {d0, d1, d2, d3};
        #pragma unroll
        for (int ii = 0; ii < 4; ii++) {
            int qi = qb * 4 + ii;
            float lg = dots[ii] * scale;
            if (kglob > q0 + qi) lg = -INFINITY;
            Ls[qi][kj] = lg;
        }
        __syncthreads();

        if (tid < 16) {
            float tm = -INFINITY;
            #pragma unroll
            for (int jj = 0; jj < 32; jj++) tm = fmaxf(tm, Ls[tid][jj]);
            float mo = Ms[tid];
            float nm = fmaxf(mo, tm);
            Corr[tid] = expf(mo - nm);
            Ms[tid] = nm;
        }
        __syncthreads();

        #pragma unroll
        for (int e = tid; e < 512; e += 128) {
            int qi = e >> 5, jj = e & 31;
            Ls[qi][jj] = expf(Ls[qi][jj] - Ms[qi]);
        }
        __syncthreads();

        if (tid < 16) {
            float ts = 0.f;
            #pragma unroll
            for (int jj = 0; jj < 32; jj++) ts += Ls[tid][jj];
            Lsum[tid] = Lsum[tid] * Corr[tid] + ts;
        }

        #pragma unroll
        for (int qi = 0; qi < 16; qi++) acc[qi] *= Corr[qi];
        #pragma unroll 4
        for (int jj = 0; jj < 32; jj++) {
            float vj = Vs[jj][tid];
            #pragma unroll
            for (int qi = 0; qi < 16; qi++) acc[qi] += Ls[qi][jj] * vj;
        }
        __syncthreads();
    }

    #pragma unroll
    for (int qi = 0; qi < 16; qi++)
        O[(size_t)(q0 + qi) * (NH * HD) + h * HD + tid] = __float2half_rn(acc[qi] / Lsum[qi]);
}

// ============================ launch =========================================
extern "C" void kernel_launch(void* const* d_in, const int* in_sizes, int n_in,
                              void* d_out, int out_size) {
    const float* x   = (const float*)d_in[0];
    const float* cs  = (const float*)d_in[1];
    const float* sn  = (const float*)d_in[2];
    const float* wq  = (const float*)d_in[3];
    const float* wk  = (const float*)d_in[4];
    const float* wv  = (const float*)d_in[5];
    const float* wo  = (const float*)d_in[6];
    const float* wg  = (const float*)d_in[7];
    const float* wu  = (const float*)d_in[8];
    const float* wd  = (const float*)d_in[9];
    const float* ln1 = (const float*)d_in[10];
    const float* ln2 = (const float*)d_in[11];
    float* out = (float*)d_out;

    __half *p_wqkv, *p_wot, *p_wgt, *p_wut, *p_wdt;
    float *p_sqkv, *p_swo, *p_swg, *p_swu, *p_swd;
    __half *p_hhi, *p_hlo, *p_h2, *p_o, *p_G;
    float *p_qkv, *p_x2, *p_U;
    cudaGetSymbolAddress((void**)&p_wqkv, g_wqkv);
    cudaGetSymbolAddress((void**)&p_wot, g_wot);
    cudaGetSymbolAddress((void**)&p_wgt, g_wgt);
    cudaGetSymbolAddress((void**)&p_wut, g_wut);
    cudaGetSymbolAddress((void**)&p_wdt, g_wdt);
    cudaGetSymbolAddress((void**)&p_sqkv, g_sqkv);
    cudaGetSymbolAddress((void**)&p_swo, g_swo);
    cudaGetSymbolAddress((void**)&p_swg, g_swg);
    cudaGetSymbolAddress((void**)&p_swu, g_swu);
    cudaGetSymbolAddress((void**)&p_swd, g_swd);
    cudaGetSymbolAddress((void**)&p_hhi, g_hhi);
    cudaGetSymbolAddress((void**)&p_hlo, g_hlo);
    cudaGetSymbolAddress((void**)&p_h2,  g_h2);
    cudaGetSymbolAddress((void**)&p_o,   g_o);
    cudaGetSymbolAddress((void**)&p_G,   g_G);
    cudaGetSymbolAddress((void**)&p_qkv, g_qkv);
    cudaGetSymbolAddress((void**)&p_x2,  g_x2);
    cudaGetSymbolAddress((void**)&p_U,   g_U);

    const int SM2 = 3 * (2 * ABUF + BBUF);   // two-pass stages (122880)
    const int SM1 = 3 * (ABUF + BBUF);       // single-pass stages (92160)
    cudaFuncSetAttribute(tc_gemm<0, true>,  cudaFuncAttributeMaxDynamicSharedMemorySize, SM2);
    cudaFuncSetAttribute(tc_gemm<0, false>, cudaFuncAttributeMaxDynamicSharedMemorySize, SM1);
    cudaFuncSetAttribute(tc_gemm<1, false>, cudaFuncAttributeMaxDynamicSharedMemorySize, SM1);
    cudaFuncSetAttribute(tc_gemm<3, false>, cudaFuncAttributeMaxDynamicSharedMemorySize, SM1);

    // ---- ordered so my launch #4 (harness skips 2 + ncu -s 5) is QKV GEMM ----
    quant_qkv_kernel<<<NQKV, 256>>>(wq, wk, wv, p_wqkv, p_sqkv);                            // 1
    rmsnorm_kernel<true><<<S_LEN, 256>>>(x, ln1, p_hhi, p_hlo);                             // 2
    quant_kernel<<<HID, 256>>>(wo, p_wot, p_swo, HID);                                      // 3
    dim3 gQKV(NQKV / 256, S_LEN / 128);   // (12,16)
    tc_gemm<0, true><<<gQKV, 256, SM2>>>(p_hhi, p_hlo, p_wqkv, p_sqkv,                      // 4 (profiled)
                                         p_qkv, nullptr, nullptr, S_LEN, NQKV, HID);
    quant_kernel<<<INTER, 256>>>(wg, p_wgt, p_swg, HID);                                    // 5
    quant_kernel<<<INTER, 256>>>(wu, p_wut, p_swu, HID);                                    // 6
    quant_kernel<<<HID,   256>>>(wd, p_wdt, p_swd, INTER);                                  // 7
    rope_kernel<<<(S_LEN * NH  * 64) / 256, 256>>>(p_qkv, cs, sn, NH, 0);                   // 8
    rope_kernel<<<(S_LEN * NKV * 64) / 256, 256>>>(p_qkv, cs, sn, NKV, 2048);               // 9
    attn_kernel<<<dim3(S_LEN / 16, NH), 128>>>(p_qkv, p_o);                                 // 10
    dim3 gO(HID / 256, S_LEN / 128);      // (8,16)
    tc_gemm<1, false><<<gO, 256, SM1>>>(p_o, nullptr, p_wot, p_swo,                         // 11
                                        p_x2, x, nullptr, S_LEN, HID, HID);
    rmsnorm_kernel<false><<<S_LEN, 256>>>(p_x2, ln2, p_h2, nullptr);                        // 12
    dim3 gI(INTER / 256, S_LEN / 128);    // (32,16)
    tc_gemm<0, false><<<gI, 256, SM1>>>(p_h2, nullptr, p_wut, p_swu,                        // 13
                                        p_U, nullptr, nullptr, S_LEN, INTER, HID);
    tc_gemm<3, false><<<gI, 256, SM1>>>(p_h2, nullptr, p_wgt, p_swg,                        // 14
                                        nullptr, p_U, p_G, S_LEN, INTER, HID);
    tc_gemm<1, false><<<gO, 256, SM1>>>(p_G, nullptr, p_wdt, p_swd,                         // 15
                                        out, p_x2, nullptr, S_LEN, HID, INTER);
}